// round 12
// baseline (speedup 1.0000x reference)
#include <cuda_runtime.h>
#include <cuda_bf16.h>

#define B_    8
#define NUM_  128
#define L_    (NUM_ * NUM_)     // 16384
#define H_    8
#define TOPK_ 4
#define NROWS_ (B_ * NUM_)      // 1024 (b,i) rows
#define NC_    8                // chunks per row (16 j each)

// Scratch (allocation-free rule: __device__ globals)
__device__ float              g_cval[NROWS_ * H_ * NC_ * TOPK_];  // candidate values
__device__ unsigned           g_cidx[NROWS_ * H_ * NC_];          // packed 4x8bit local idx
__device__ unsigned long long g_maskbits[2];                      // 128-bit column mask
__device__ unsigned           g_donecnt;                          // merge completion counter

// ---------------------------------------------------------------------------
// Kernel 1: block = (b,i,chunk). Cosine+relu for 16 j x 8 h, multiply by roi,
// write DIRECTLY to out, emit per-head per-chunk top-4 candidates.
// (Round-7 streamer: 84-85.5us across runs, DRAM ~81% — at its BW floor.)
// ---------------------------------------------------------------------------
__global__ __launch_bounds__(256, 6) void fused_kernel(
    const float4* __restrict__ q4, const float4* __restrict__ k4,
    const float* __restrict__ roi, float* __restrict__ out)
{
    __shared__ float s_attn[16 * 9];            // local j x head, pitch 9

    const int blk  = blockIdx.x;
    const int bi   = blk >> 3;                  // (b,i) row
    const int chk  = blk & 7;                   // 16-j chunk
    const int tid  = threadIdx.x;
    const int warp = tid >> 5;
    const int lane = tid & 31;
    const int head = lane >> 2;
    const int sub  = lane & 3;

    if (blk == 0 && tid < 2) g_maskbits[tid] = 0ull;  // reset per replay
                                                      // (ordered by launch boundary)
    const size_t rowBase = (size_t)bi * (NUM_ * 128) + (size_t)chk * (16 * 128);

    // ---- warp computes its two j's: 16 LDG.128 front-batched ----
    {
        const int jl0 = warp * 2;
        const size_t base0 = rowBase + (size_t)jl0 * 128;
        const size_t base1 = base0 + 128;

        float dot0 = 0.f, qq0 = 0.f, kk0 = 0.f;
        float dot1 = 0.f, qq1 = 0.f, kk1 = 0.f;
        #pragma unroll
        for (int t = 0; t < 4; ++t) {
            const int idx = head * 16 + t * 4 + sub;
            const float4 qa = __ldcs(&q4[base0 + idx]);
            const float4 ka = __ldcs(&k4[base0 + idx]);
            const float4 qb = __ldcs(&q4[base1 + idx]);
            const float4 kb = __ldcs(&k4[base1 + idx]);
            dot0 += qa.x*ka.x + qa.y*ka.y + qa.z*ka.z + qa.w*ka.w;
            qq0  += qa.x*qa.x + qa.y*qa.y + qa.z*qa.z + qa.w*qa.w;
            kk0  += ka.x*ka.x + ka.y*ka.y + ka.z*ka.z + ka.w*ka.w;
            dot1 += qb.x*kb.x + qb.y*kb.y + qb.z*kb.z + qb.w*kb.w;
            qq1  += qb.x*qb.x + qb.y*qb.y + qb.z*qb.z + qb.w*qb.w;
            kk1  += kb.x*kb.x + kb.y*kb.y + kb.z*kb.z + kb.w*kb.w;
        }
        #pragma unroll
        for (int off = 1; off <= 2; off <<= 1) {
            dot0 += __shfl_xor_sync(0xffffffffu, dot0, off);
            qq0  += __shfl_xor_sync(0xffffffffu, qq0,  off);
            kk0  += __shfl_xor_sync(0xffffffffu, kk0,  off);
            dot1 += __shfl_xor_sync(0xffffffffu, dot1, off);
            qq1  += __shfl_xor_sync(0xffffffffu, qq1,  off);
            kk1  += __shfl_xor_sync(0xffffffffu, kk1,  off);
        }
        if (sub == 0) {
            float d0 = fmaxf(sqrtf(qq0) * sqrtf(kk0), 1e-8f);
            float d1 = fmaxf(sqrtf(qq1) * sqrtf(kk1), 1e-8f);
            s_attn[jl0 * 9 + head]       = fmaxf(dot0 / d0, 0.0f);
            s_attn[(jl0 + 1) * 9 + head] = fmaxf(dot1 / d1, 0.0f);
        }
    }
    __syncthreads();

    // ---- writeback: out[b,i,j,h] = attn * roi[b,i,j] (mask applied later) ----
    if (tid < 128) {
        const int jl = tid >> 3;                          // local j
        const float s = __ldg(&roi[bi * NUM_ + chk * 16 + jl]);
        const size_t gbase = (size_t)bi * (NUM_ * H_) + (size_t)chk * (16 * H_);
        out[gbase + tid] = s_attn[jl * 9 + (tid & 7)] * s;
    }

    // ---- per-head top-4 within this 16-j chunk: warp w = head w ----
    {
        float v;
        int   jl;
        if (lane < 16) { v = s_attn[lane * 9 + warp]; jl = lane; }
        else           { v = -1e30f;                  jl = 255;  }
        unsigned packed = 0;
        const int rbase = ((bi * H_ + warp) * NC_ + chk) * TOPK_;
        #pragma unroll
        for (int r = 0; r < TOPK_; ++r) {
            float bv = v; int bj = jl;
            #pragma unroll
            for (int off = 16; off > 0; off >>= 1) {
                const float ov = __shfl_xor_sync(0xffffffffu, bv, off);
                const int   oj = __shfl_xor_sync(0xffffffffu, bj, off);
                if (ov > bv || (ov == bv && oj < bj)) { bv = ov; bj = oj; }
            }
            packed |= ((unsigned)bj) << (8 * r);
            if (jl == bj) v = -1e30f;           // remove winner
            if (lane == 0) g_cval[rbase + r] = bv;
        }
        if (lane == 0) g_cidx[(bi * H_ + warp) * NC_ + chk] = packed;
    }
}

// ---------------------------------------------------------------------------
// Kernel 2: merge + fixup, 32 blocks. One THREAD per (b,i,h) row: streaming
// insertion of 32 candidates into a running top-4 in named scalars (fully
// predicated compare-shift: no arrays, no spills, no shuffles). Mask union
// via shared u64 -> one global atomicOr per block. The 32nd-arriving block
// zeros unmasked output columns (near-nop when mask is full; exact always).
// Fence/atomic serialization at 32 blocks is ~1k cycles (vs 1024-block
// variants that measured 12.7us) — off the critical path.
// ---------------------------------------------------------------------------
__global__ __launch_bounds__(256) void merge_fixup_kernel(float4* __restrict__ out4)
{
    __shared__ unsigned long long s_lo, s_hi;
    __shared__ unsigned s_final;
    const int tid = threadIdx.x;
    if (tid == 0) { s_lo = 0ull; s_hi = 0ull; }
    __syncthreads();

    const int r = blockIdx.x * blockDim.x + tid;   // 0..8191

    float v0 = -1e30f, v1 = -1e30f, v2 = -1e30f, v3 = -1e30f;
    int   j0 = 1 << 20, j1 = 1 << 20, j2 = 1 << 20, j3 = 1 << 20;

#define INSERT_CAND(cv, cj)                                                   \
    do {                                                                      \
        const float _v = (cv); const int _j = (cj);                           \
        const bool b0 = (_v > v0) || (_v == v0 && _j < j0);                   \
        const bool b1 = (_v > v1) || (_v == v1 && _j < j1);                   \
        const bool b2 = (_v > v2) || (_v == v2 && _j < j2);                   \
        const bool b3 = (_v > v3) || (_v == v3 && _j < j3);                   \
        if (b0)      { v3=v2; j3=j2; v2=v1; j2=j1; v1=v0; j1=j0; v0=_v; j0=_j; } \
        else if (b1) { v3=v2; j3=j2; v2=v1; j2=j1; v1=_v; j1=_j; }            \
        else if (b2) { v3=v2; j3=j2; v2=_v; j2=_j; }                          \
        else if (b3) { v3=_v; j3=_j; }                                        \
    } while (0)

    const float4* cv4 = (const float4*)&g_cval[r * (NC_ * TOPK_)];
    #pragma unroll
    for (int q = 0; q < NC_; ++q) {
        const float4 c = cv4[q];
        const unsigned w = g_cidx[r * NC_ + q];
        const int jb = q * 16;
        INSERT_CAND(c.x, jb + (int)((w      ) & 255u));
        INSERT_CAND(c.y, jb + (int)((w >>  8) & 255u));
        INSERT_CAND(c.z, jb + (int)((w >> 16) & 255u));
        INSERT_CAND(c.w, jb + (int)((w >> 24) & 255u));
    }
#undef INSERT_CAND

    unsigned long long lo = 0ull, hi = 0ull;
#define SET_BIT(jj)                                                           \
    do { if ((jj) < 64) lo |= 1ull << (jj); else hi |= 1ull << ((jj) - 64); } while (0)
    SET_BIT(j0); SET_BIT(j1); SET_BIT(j2); SET_BIT(j3);
#undef SET_BIT

    if (lo) atomicOr(&s_lo, lo);
    if (hi) atomicOr(&s_hi, hi);
    __syncthreads();
    if (tid == 0) {
        if (s_lo) atomicOr(&g_maskbits[0], s_lo);
        if (s_hi) atomicOr(&g_maskbits[1], s_hi);
    }

    // ---- last-arriving block performs the column fixup ----
    __threadfence();                            // publish this block's mask bits
    __syncthreads();
    if (tid == 0)
        s_final = ((atomicAdd(&g_donecnt, 1u) & 31u) == 31u) ? 1u : 0u;
    __syncthreads();
    if (!s_final) return;
    __threadfence();                            // acquire all blocks' mask bits

    const unsigned long long mlo = g_maskbits[0];
    const unsigned long long mhi = g_maskbits[1];
    const float4 z = make_float4(0.f, 0.f, 0.f, 0.f);
    for (int j = 0; j < NUM_; ++j) {
        const unsigned long long w = (j < 64) ? mlo : mhi;
        if ((w >> (j & 63)) & 1ull) continue;   // column survives
        #pragma unroll
        for (int t = 0; t < 4; ++t) {
            const int bi = tid + t * 256;                  // 0..1023
            const size_t base = ((size_t)bi * NUM_ + j) * 2;
            out4[base]     = z;
            out4[base + 1] = z;
        }
    }
}

// ---------------------------------------------------------------------------
extern "C" void kernel_launch(void* const* d_in, const int* in_sizes, int n_in,
                              void* d_out, int out_size)
{
    const float4* q4  = (const float4*)d_in[0];
    const float4* k4  = (const float4*)d_in[1];
    const float*  roi = (const float*)d_in[2];
    float*        out = (float*)d_out;

    fused_kernel<<<NROWS_ * NC_, 256>>>(q4, k4, roi, out);   // 8192 blocks
    merge_fixup_kernel<<<32, 256>>>((float4*)out);           // 32 blocks
}

// round 14
// speedup vs baseline: 1.0495x; 1.0495x over previous
#include <cuda_runtime.h>
#include <cuda_bf16.h>

#define B_    8
#define NUM_  128
#define L_    (NUM_ * NUM_)     // 16384
#define H_    8
#define TOPK_ 4
#define NROWS_ (B_ * NUM_)      // 1024 (b,i) rows
#define NC_    8                // chunks per row (16 j each)

// Scratch (allocation-free rule: __device__ globals)
// Candidate = packed u64: (float_bits(value) << 32) | (127 - j).
// value >= 0 so float bits are monotone; low word breaks ties toward smaller j.
__device__ unsigned long long g_cand[NROWS_ * H_ * NC_ * TOPK_];  // 2 MB
__device__ unsigned long long g_maskbits[2];                      // 128-bit column mask

// ---------------------------------------------------------------------------
// Kernel 1: block = (b,i,chunk). Cosine+relu for 16 j x 8 h, multiply by roi,
// write DIRECTLY to out, emit per-head per-chunk top-4 packed candidates.
// (Streamer unchanged since R7: 84-85.5us, DRAM ~81% — at its BW floor.)
// ---------------------------------------------------------------------------
__global__ __launch_bounds__(256, 6) void fused_kernel(
    const float4* __restrict__ q4, const float4* __restrict__ k4,
    const float* __restrict__ roi, float* __restrict__ out)
{
    __shared__ float s_attn[16 * 9];            // local j x head, pitch 9

    const int blk  = blockIdx.x;
    const int bi   = blk >> 3;                  // (b,i) row
    const int chk  = blk & 7;                   // 16-j chunk
    const int tid  = threadIdx.x;
    const int warp = tid >> 5;
    const int lane = tid & 31;
    const int head = lane >> 2;
    const int sub  = lane & 3;

    if (blk == 0 && tid < 2) g_maskbits[tid] = 0ull;  // reset per replay
                                                      // (launch-boundary ordered)
    const size_t rowBase = (size_t)bi * (NUM_ * 128) + (size_t)chk * (16 * 128);

    // ---- warp computes its two j's: 16 LDG.128 front-batched ----
    {
        const int jl0 = warp * 2;
        const size_t base0 = rowBase + (size_t)jl0 * 128;
        const size_t base1 = base0 + 128;

        float dot0 = 0.f, qq0 = 0.f, kk0 = 0.f;
        float dot1 = 0.f, qq1 = 0.f, kk1 = 0.f;
        #pragma unroll
        for (int t = 0; t < 4; ++t) {
            const int idx = head * 16 + t * 4 + sub;
            const float4 qa = __ldcs(&q4[base0 + idx]);
            const float4 ka = __ldcs(&k4[base0 + idx]);
            const float4 qb = __ldcs(&q4[base1 + idx]);
            const float4 kb = __ldcs(&k4[base1 + idx]);
            dot0 += qa.x*ka.x + qa.y*ka.y + qa.z*ka.z + qa.w*ka.w;
            qq0  += qa.x*qa.x + qa.y*qa.y + qa.z*qa.z + qa.w*qa.w;
            kk0  += ka.x*ka.x + ka.y*ka.y + ka.z*ka.z + ka.w*ka.w;
            dot1 += qb.x*kb.x + qb.y*kb.y + qb.z*kb.z + qb.w*kb.w;
            qq1  += qb.x*qb.x + qb.y*qb.y + qb.z*qb.z + qb.w*qb.w;
            kk1  += kb.x*kb.x + kb.y*kb.y + kb.z*kb.z + kb.w*kb.w;
        }
        #pragma unroll
        for (int off = 1; off <= 2; off <<= 1) {
            dot0 += __shfl_xor_sync(0xffffffffu, dot0, off);
            qq0  += __shfl_xor_sync(0xffffffffu, qq0,  off);
            kk0  += __shfl_xor_sync(0xffffffffu, kk0,  off);
            dot1 += __shfl_xor_sync(0xffffffffu, dot1, off);
            qq1  += __shfl_xor_sync(0xffffffffu, qq1,  off);
            kk1  += __shfl_xor_sync(0xffffffffu, kk1,  off);
        }
        if (sub == 0) {
            float d0 = fmaxf(sqrtf(qq0) * sqrtf(kk0), 1e-8f);
            float d1 = fmaxf(sqrtf(qq1) * sqrtf(kk1), 1e-8f);
            s_attn[jl0 * 9 + head]       = fmaxf(dot0 / d0, 0.0f);
            s_attn[(jl0 + 1) * 9 + head] = fmaxf(dot1 / d1, 0.0f);
        }
    }
    __syncthreads();

    // ---- writeback: out[b,i,j,h] = attn * roi[b,i,j] (mask applied later) ----
    if (tid < 128) {
        const int jl = tid >> 3;                          // local j
        const float s = __ldg(&roi[bi * NUM_ + chk * 16 + jl]);
        const size_t gbase = (size_t)bi * (NUM_ * H_) + (size_t)chk * (16 * H_);
        out[gbase + tid] = s_attn[jl * 9 + (tid & 7)] * s;
    }

    // ---- per-head top-4 within this 16-j chunk (packed u64, branchless) ----
    {
        unsigned long long key = 0ull;
        if (lane < 16) {
            const float v = s_attn[lane * 9 + warp];      // conflict-free
            const int jglob = chk * 16 + lane;
            key = ((unsigned long long)__float_as_uint(v) << 32)
                | (unsigned long long)(unsigned)(127 - jglob);
        }
        const int rbase = ((bi * H_ + warp) * NC_ + chk) * TOPK_;
        #pragma unroll
        for (int r = 0; r < TOPK_; ++r) {
            unsigned long long bk = key;
            #pragma unroll
            for (int off = 16; off > 0; off >>= 1) {
                const unsigned long long ok = __shfl_xor_sync(0xffffffffu, bk, off);
                bk = (ok > bk) ? ok : bk;                 // SEL, no branch
            }
            if (lane == 0) g_cand[rbase + r] = bk;
            if (key == bk) key = 0ull;                    // remove winner
        }
    }
}

// ---------------------------------------------------------------------------
// Kernel 2: merge. One THREAD per (b,i,h) row: 16 coalesced ulonglong2 loads,
// 32-step branchless compare-swap insertion into a running top-4 (named
// scalars, single u64 compare per level -> pure SEL, no divergence, no
// spills). Winners' j bits union'd into the 128-bit mask.
// ---------------------------------------------------------------------------
__global__ __launch_bounds__(256) void merge_kernel()
{
    __shared__ unsigned long long s_lo, s_hi;
    const int tid = threadIdx.x;
    if (tid == 0) { s_lo = 0ull; s_hi = 0ull; }
    __syncthreads();

    const int r = blockIdx.x * blockDim.x + tid;   // 0..8191

    unsigned long long k0 = 0ull, k1 = 0ull, k2 = 0ull, k3 = 0ull;

#define INS(xx)                                                               \
    do {                                                                      \
        unsigned long long p = (xx), t;                                       \
        bool c;                                                               \
        c = p > k0; t = k0; k0 = c ? p : k0; p = c ? t : p;                   \
        c = p > k1; t = k1; k1 = c ? p : k1; p = c ? t : p;                   \
        c = p > k2; t = k2; k2 = c ? p : k2; p = c ? t : p;                   \
        c = p > k3; k3 = c ? p : k3;                                          \
    } while (0)

    const ulonglong2* c2 = (const ulonglong2*)&g_cand[(size_t)r * (NC_ * TOPK_)];
    #pragma unroll
    for (int q = 0; q < 16; ++q) {
        const ulonglong2 c = c2[q];
        INS(c.x);
        INS(c.y);
    }
#undef INS

    unsigned long long lo = 0ull, hi = 0ull;
#define SET_BIT(kk)                                                           \
    do {                                                                      \
        const int jj = 127 - (int)((unsigned)(kk) & 0xFFFFFFFFu);             \
        if (jj < 64) lo |= 1ull << jj; else hi |= 1ull << (jj - 64);          \
    } while (0)
    SET_BIT(k0); SET_BIT(k1); SET_BIT(k2); SET_BIT(k3);
#undef SET_BIT

    if (lo) atomicOr(&s_lo, lo);
    if (hi) atomicOr(&s_hi, hi);
    __syncthreads();
    if (tid == 0) {
        if (s_lo) atomicOr(&g_maskbits[0], s_lo);
        if (s_hi) atomicOr(&g_maskbits[1], s_hi);
    }
}

// ---------------------------------------------------------------------------
// Kernel 3: fixup. Block j: if mask[j]==0, zero out[:, :, j, :]. Near-nop
// when the union mask is full (common case); exact in all cases.
// ---------------------------------------------------------------------------
__global__ __launch_bounds__(256) void fixup_kernel(float4* __restrict__ out)
{
    const int j = blockIdx.x;
    const unsigned long long w = g_maskbits[j >> 6];
    if ((w >> (j & 63)) & 1ull) return;                  // column survives

    const float4 z = make_float4(0.f, 0.f, 0.f, 0.f);
    #pragma unroll
    for (int t = 0; t < 4; ++t) {
        const int bi = threadIdx.x + t * 256;            // 0..1023
        const size_t base = ((size_t)bi * NUM_ + j) * 2; // float4 units
        out[base]     = z;
        out[base + 1] = z;
    }
}

// ---------------------------------------------------------------------------
extern "C" void kernel_launch(void* const* d_in, const int* in_sizes, int n_in,
                              void* d_out, int out_size)
{
    const float4* q4  = (const float4*)d_in[0];
    const float4* k4  = (const float4*)d_in[1];
    const float*  roi = (const float*)d_in[2];
    float*        out = (float*)d_out;

    fused_kernel<<<NROWS_ * NC_, 256>>>(q4, k4, roi, out);  // 8192 blocks
    merge_kernel<<<(NROWS_ * H_) / 256, 256>>>();           // 32 blocks
    fixup_kernel<<<NUM_, 256>>>((float4*)out);              // 128 blocks
}